// round 13
// baseline (speedup 1.0000x reference)
#include <cuda_runtime.h>
#include <float.h>

#define NDET      5000
#define TOPK      1000
#define NCLS      80
#define DETSTRIDE 84
#define CH        256
#define CROP      14

// Scratch (no allocations allowed in kernel_launch)
__device__ float g_scores[NDET];
__device__ int   g_sel[TOPK];            // rank -> original detection row
__device__ float4 g_boxes[TOPK];         // boxes after stable level sort
__device__ int    g_level[TOPK];

// ---------------------------------------------------------------------------
// K1: per-row max over 80 class scores. Warp per row, coalesced reads.
// ---------------------------------------------------------------------------
__global__ void __launch_bounds__(256) k_scores(const float* __restrict__ det) {
    int warp = (blockIdx.x * blockDim.x + threadIdx.x) >> 5;
    int lane = threadIdx.x & 31;
    if (warp >= NDET) return;
    const float* p = det + (size_t)warp * DETSTRIDE + 4;
    float m = -FLT_MAX;
    for (int i = lane; i < NCLS; i += 32) m = fmaxf(m, p[i]);
#pragma unroll
    for (int off = 16; off > 0; off >>= 1)
        m = fmaxf(m, __shfl_xor_sync(0xffffffffu, m, off));
    if (lane == 0) g_scores[warp] = m;
}

// ---------------------------------------------------------------------------
// K2: exact jax.lax.top_k via rank counting. 8 rows per block (5000/8 = 625
// blocks, exact), scores staged in shared once; 512 threads split compares.
// ---------------------------------------------------------------------------
#define RPB 8
__global__ void __launch_bounds__(512) k_rank() {
    __shared__ float s[NDET];
    __shared__ int blockcnt[RPB];
    int tid = threadIdx.x;
    for (int j = tid; j < NDET; j += 512) s[j] = g_scores[j];
    if (tid < RPB) blockcnt[tid] = 0;
    __syncthreads();

    int base = blockIdx.x * RPB;
    float sr[RPB];
#pragma unroll
    for (int k = 0; k < RPB; k++) sr[k] = s[base + k];

    int cnt[RPB];
#pragma unroll
    for (int k = 0; k < RPB; k++) cnt[k] = 0;

    for (int j = tid; j < NDET; j += 512) {
        float sj = s[j];
#pragma unroll
        for (int k = 0; k < RPB; k++)
            cnt[k] += (sj > sr[k] || (sj == sr[k] && j < base + k)) ? 1 : 0;
    }
#pragma unroll
    for (int k = 0; k < RPB; k++) {
#pragma unroll
        for (int off = 16; off > 0; off >>= 1)
            cnt[k] += __shfl_down_sync(0xffffffffu, cnt[k], off);
    }
    if ((tid & 31) == 0) {
#pragma unroll
        for (int k = 0; k < RPB; k++) atomicAdd(&blockcnt[k], cnt[k]);
    }
    __syncthreads();
    if (tid < RPB) {
        int rank = blockcnt[tid];
        if (rank < TOPK) g_sel[rank] = base + tid;
    }
}

// ---------------------------------------------------------------------------
// K3: fused level computation + stable counting sort by level (single block).
// ---------------------------------------------------------------------------
__global__ void __launch_bounds__(1024) k_level_sort(const float* __restrict__ det) {
    int r = threadIdx.x;
    float x1 = 0, y1 = 0, x2 = 0, y2 = 0;
    int lev = 0;
    unsigned long long onehot = 0ULL;
    if (r < TOPK) {
        const float* p = det + (size_t)g_sel[r] * DETSTRIDE;
        x1 = p[0]; y1 = p[1]; x2 = p[2]; y2 = p[3];
        float size = sqrtf((x2 - x1) * (y2 - y1));
        float lv = floorf(1.0f + log2f(size / 224.0f + 1e-7f));
        lv = fminf(fmaxf(lv, 0.0f), 4.0f);
        lev = (int)lv;
        onehot = 1ULL << (10 * lev);
    }
    unsigned long long v = onehot;
    int lane = r & 31;
#pragma unroll
    for (int off = 1; off < 32; off <<= 1) {
        unsigned long long n = __shfl_up_sync(0xffffffffu, v, off);
        if (lane >= off) v += n;
    }
    __shared__ unsigned long long warpsum[32];
    int wid = r >> 5;
    if (lane == 31) warpsum[wid] = v;
    __syncthreads();
    if (r < 32) {
        unsigned long long w = warpsum[r];
#pragma unroll
        for (int off = 1; off < 32; off <<= 1) {
            unsigned long long n = __shfl_up_sync(0xffffffffu, w, off);
            if (r >= off) w += n;
        }
        warpsum[r] = w;
    }
    __syncthreads();
    unsigned long long incl = v + (wid > 0 ? warpsum[wid - 1] : 0ULL);
    unsigned long long total = warpsum[31];
    unsigned long long excl = incl - onehot;
    if (r < TOPK) {
        int before = 0;
#pragma unroll
        for (int l = 0; l < 4; l++)
            if (l < lev) before += (int)((total >> (10 * l)) & 1023ULL);
        int pos = before + (int)((excl >> (10 * lev)) & 1023ULL);
        g_boxes[pos] = make_float4(x1, y1, x2, y2);
        g_level[pos] = lev;
    }
}

// ---------------------------------------------------------------------------
// K4: crop_and_resize. 128-thread block = (box, y-half), fixed grid 2000.
// Valid x-columns compacted + padded to multiple of 4; hot loop does
// 4 points/iter = 16 independent LDG.128 per thread. launch_bounds(128,6)
// forces <=85 regs so 6 blocks/SM fit at unchanged 16-wide MLP.
// ---------------------------------------------------------------------------
__global__ void __launch_bounds__(128, 6) k_main(
    const float* __restrict__ p0, const float* __restrict__ p1,
    const float* __restrict__ p2, const float* __restrict__ p3,
    const float* __restrict__ p4, float* __restrict__ out)
{
    __shared__ float s_lx[CROP], s_ly[CROP];
    __shared__ int   s_x0[CROP], s_x1[CROP];   // float4 offsets within a row
    __shared__ int   s_r0[CROP], s_r1[CROP];   // float4 offsets of rows
    __shared__ int   s_vx[CROP], s_vy[CROP];
    __shared__ int   s_xlist[CROP + 3], s_xinv[CROP];
    __shared__ int   s_nx, s_ninv;

    int tid  = threadIdx.x;
    int b    = blockIdx.x >> 1;
    int half = blockIdx.x & 1;
    float4 box = g_boxes[b];
    int lev = g_level[b];

    const float* feat;
    int S;
    switch (lev) {
        case 0:  feat = p0; S = 256; break;
        case 1:  feat = p1; S = 128; break;
        case 2:  feat = p2; S = 64;  break;
        case 3:  feat = p3; S = 32;  break;
        default: feat = p4; S = 16;  break;
    }
    float hf = (float)(S - 1);

    if (tid < 2 * CROP) {
        int i = tid;
        bool isy = i >= CROP;
        int k = isy ? i - CROP : i;
        float a1 = isy ? box.y : box.x;
        float a2 = isy ? box.w : box.z;
        // reference normalizes then rescales by the same (S-1) factor
        float n1 = a1 / hf, n2 = a2 / hf;
        float t = (float)k / 13.0f;
        float s = (n1 + (n2 - n1) * t) * hf;
        int valid = (s >= 0.0f && s <= hf) ? 1 : 0;
        float f0 = floorf(s);
        float l = s - f0;
        int i0 = (int)fminf(fmaxf(f0, 0.0f), hf);
        int i1 = (int)fminf(fmaxf(f0 + 1.0f, 0.0f), hf);
        if (isy) {
            s_ly[k] = l; s_vy[k] = valid;
            s_r0[k] = i0 * S * (CH / 4);
            s_r1[k] = i1 * S * (CH / 4);
        } else {
            s_lx[k] = l; s_vx[k] = valid;
            s_x0[k] = i0 * (CH / 4);
            s_x1[k] = i1 * (CH / 4);
        }
    }
    __syncthreads();
    if (tid == 0) {
        int n = 0, m = 0;
#pragma unroll
        for (int i = 0; i < CROP; i++) {
            if (s_vx[i]) s_xlist[n++] = i;
            else         s_xinv[m++]  = i;
        }
        s_nx = n; s_ninv = m;
        if (n > 0) {                      // pad to multiple of 4
            int last = s_xlist[n - 1];
            while (n & 3) s_xlist[n++] = last;
        }
    }
    __syncthreads();

    int cg = tid & 63;           // channel group (float4)
    int rg = tid >> 6;           // row group (0..1)
    const float4* fp = (const float4*)feat;
    const float4 zero4 = make_float4(0.f, 0.f, 0.f, 0.f);
    int nv = s_nx, ni = s_ninv;
    int nvp = (nv + 3) & ~3;
    int ybase = half * 7;        // rows [ybase, ybase+7)

    for (int yi = ybase + rg; yi < ybase + 7; yi += 2) {
        float4* orow = (float4*)(out + (((size_t)b * CROP + yi) * CROP) * CH) + cg;

        if (!s_vy[yi]) {
#pragma unroll
            for (int xi = 0; xi < CROP; xi++)
                __stcs(orow + (size_t)xi * 64, zero4);
            continue;
        }

        // zero-fill invalid columns (no loads)
        for (int k = 0; k < ni; k++)
            __stcs(orow + (size_t)s_xinv[k] * 64, zero4);

        int r0 = s_r0[yi] + cg;
        int r1 = s_r1[yi] + cg;
        float ly = s_ly[yi];

        for (int j = 0; j < nvp; j += 4) {
            int   xq[4];
            int   q0[4], q1[4];
            float lx[4];
#pragma unroll
            for (int q = 0; q < 4; q++) {
                xq[q] = s_xlist[j + q];
                q0[q] = s_x0[xq[q]];
                q1[q] = s_x1[xq[q]];
                lx[q] = s_lx[xq[q]];
            }
            float4 F00[4], F01[4], F10[4], F11[4];
#pragma unroll
            for (int q = 0; q < 4; q++) {
                F00[q] = __ldg(fp + r0 + q0[q]);
                F01[q] = __ldg(fp + r0 + q1[q]);
                F10[q] = __ldg(fp + r1 + q0[q]);
                F11[q] = __ldg(fp + r1 + q1[q]);
            }
#pragma unroll
            for (int q = 0; q < 4; q++) {
                float4 v;
                float t, bo;
                t = F00[q].x + (F01[q].x - F00[q].x) * lx[q];
                bo = F10[q].x + (F11[q].x - F10[q].x) * lx[q];
                v.x = t + (bo - t) * ly;
                t = F00[q].y + (F01[q].y - F00[q].y) * lx[q];
                bo = F10[q].y + (F11[q].y - F10[q].y) * lx[q];
                v.y = t + (bo - t) * ly;
                t = F00[q].z + (F01[q].z - F00[q].z) * lx[q];
                bo = F10[q].z + (F11[q].z - F10[q].z) * lx[q];
                v.z = t + (bo - t) * ly;
                t = F00[q].w + (F01[q].w - F00[q].w) * lx[q];
                bo = F10[q].w + (F11[q].w - F10[q].w) * lx[q];
                v.w = t + (bo - t) * ly;
                __stcs(orow + (size_t)xq[q] * 64, v);
            }
        }
    }
}

// ---------------------------------------------------------------------------
extern "C" void kernel_launch(void* const* d_in, const int* in_sizes, int n_in,
                              void* d_out, int out_size) {
    const float* det = (const float*)d_in[0];
    const float* p0  = (const float*)d_in[1];
    const float* p1  = (const float*)d_in[2];
    const float* p2  = (const float*)d_in[3];
    const float* p3  = (const float*)d_in[4];
    const float* p4  = (const float*)d_in[5];
    float* out = (float*)d_out;

    k_scores<<<(NDET * 32 + 255) / 256, 256>>>(det);
    k_rank<<<NDET / RPB, 512>>>();
    k_level_sort<<<1, 1024>>>(det);
    k_main<<<TOPK * 2, 128>>>(p0, p1, p2, p3, p4, out);
}

// round 14
// speedup vs baseline: 1.0154x; 1.0154x over previous
#include <cuda_runtime.h>
#include <float.h>

#define NDET      5000
#define TOPK      1000
#define NCLS      80
#define DETSTRIDE 84
#define CH        256
#define CROP      14

// Scratch (no allocations allowed in kernel_launch)
__device__ float g_scores[NDET];
__device__ int   g_rankcnt[NDET];        // partial rank accumulators
__device__ int   g_sel[TOPK];            // rank -> original detection row
__device__ float4 g_boxes[TOPK];         // boxes after stable level sort
__device__ int    g_level[TOPK];

// ---------------------------------------------------------------------------
// K1: per-row max over 80 class scores. Warp per row, coalesced reads.
// Also zeroes the rank counters.
// ---------------------------------------------------------------------------
__global__ void __launch_bounds__(256) k_scores(const float* __restrict__ det) {
    int warp = (blockIdx.x * blockDim.x + threadIdx.x) >> 5;
    int lane = threadIdx.x & 31;
    if (warp >= NDET) return;
    const float* p = det + (size_t)warp * DETSTRIDE + 4;
    float m = -FLT_MAX;
    for (int i = lane; i < NCLS; i += 32) m = fmaxf(m, p[i]);
#pragma unroll
    for (int off = 16; off > 0; off >>= 1)
        m = fmaxf(m, __shfl_xor_sync(0xffffffffu, m, off));
    if (lane == 0) { g_scores[warp] = m; g_rankcnt[warp] = 0; }
}

// ---------------------------------------------------------------------------
// K2: exact jax.lax.top_k rank counting, j-SPLIT version.
// Grid (625, 2): blockIdx.x -> 8 rows, blockIdx.y -> 2500-score j-slice.
// Each block accumulates partial counts into g_rankcnt via atomicAdd
// (order-independent sum -> deterministic, exact).
// rank(r) = #{j : s_j > s_r} + #{j < r : s_j == s_r}
// ---------------------------------------------------------------------------
#define RPB 8
#define JCH 2500
__global__ void __launch_bounds__(512) k_rank() {
    __shared__ float s[JCH];
    __shared__ float srs[RPB];
    __shared__ int blockcnt[RPB];
    int tid = threadIdx.x;
    int base = blockIdx.x * RPB;
    int j0   = blockIdx.y * JCH;

    for (int j = tid; j < JCH; j += 512) s[j] = g_scores[j0 + j];
    if (tid < RPB) { srs[tid] = g_scores[base + tid]; blockcnt[tid] = 0; }
    __syncthreads();

    float sr[RPB];
#pragma unroll
    for (int k = 0; k < RPB; k++) sr[k] = srs[k];

    int cnt[RPB];
#pragma unroll
    for (int k = 0; k < RPB; k++) cnt[k] = 0;

    for (int j = tid; j < JCH; j += 512) {
        float sj = s[j];
        int jg = j0 + j;
#pragma unroll
        for (int k = 0; k < RPB; k++)
            cnt[k] += (sj > sr[k] || (sj == sr[k] && jg < base + k)) ? 1 : 0;
    }
#pragma unroll
    for (int k = 0; k < RPB; k++) {
#pragma unroll
        for (int off = 16; off > 0; off >>= 1)
            cnt[k] += __shfl_down_sync(0xffffffffu, cnt[k], off);
    }
    if ((tid & 31) == 0) {
#pragma unroll
        for (int k = 0; k < RPB; k++) atomicAdd(&blockcnt[k], cnt[k]);
    }
    __syncthreads();
    if (tid < RPB) atomicAdd(&g_rankcnt[base + tid], blockcnt[tid]);
}

// ---------------------------------------------------------------------------
// K2b: scatter rows into rank order.
// ---------------------------------------------------------------------------
__global__ void __launch_bounds__(256) k_scatter() {
    int r = blockIdx.x * blockDim.x + threadIdx.x;
    if (r >= NDET) return;
    int rank = g_rankcnt[r];
    if (rank < TOPK) g_sel[rank] = r;
}

// ---------------------------------------------------------------------------
// K3: fused level computation + stable counting sort by level (single block).
// ---------------------------------------------------------------------------
__global__ void __launch_bounds__(1024) k_level_sort(const float* __restrict__ det) {
    int r = threadIdx.x;
    float x1 = 0, y1 = 0, x2 = 0, y2 = 0;
    int lev = 0;
    unsigned long long onehot = 0ULL;
    if (r < TOPK) {
        const float* p = det + (size_t)g_sel[r] * DETSTRIDE;
        x1 = p[0]; y1 = p[1]; x2 = p[2]; y2 = p[3];
        float size = sqrtf((x2 - x1) * (y2 - y1));
        float lv = floorf(1.0f + log2f(size / 224.0f + 1e-7f));
        lv = fminf(fmaxf(lv, 0.0f), 4.0f);
        lev = (int)lv;
        onehot = 1ULL << (10 * lev);
    }
    unsigned long long v = onehot;
    int lane = r & 31;
#pragma unroll
    for (int off = 1; off < 32; off <<= 1) {
        unsigned long long n = __shfl_up_sync(0xffffffffu, v, off);
        if (lane >= off) v += n;
    }
    __shared__ unsigned long long warpsum[32];
    int wid = r >> 5;
    if (lane == 31) warpsum[wid] = v;
    __syncthreads();
    if (r < 32) {
        unsigned long long w = warpsum[r];
#pragma unroll
        for (int off = 1; off < 32; off <<= 1) {
            unsigned long long n = __shfl_up_sync(0xffffffffu, w, off);
            if (r >= off) w += n;
        }
        warpsum[r] = w;
    }
    __syncthreads();
    unsigned long long incl = v + (wid > 0 ? warpsum[wid - 1] : 0ULL);
    unsigned long long total = warpsum[31];
    unsigned long long excl = incl - onehot;
    if (r < TOPK) {
        int before = 0;
#pragma unroll
        for (int l = 0; l < 4; l++)
            if (l < lev) before += (int)((total >> (10 * l)) & 1023ULL);
        int pos = before + (int)((excl >> (10 * lev)) & 1023ULL);
        g_boxes[pos] = make_float4(x1, y1, x2, y2);
        g_level[pos] = lev;
    }
}

// ---------------------------------------------------------------------------
// K4: crop_and_resize. EXACT R10 config (best measured: 44.4us).
// 128-thread block = (box, y-half), grid 2000, launch_bounds(128,5).
// Valid x-columns compacted + padded to multiple of 4; 4 points/iter =
// 16 independent LDG.128 per thread.
// ---------------------------------------------------------------------------
__global__ void __launch_bounds__(128, 5) k_main(
    const float* __restrict__ p0, const float* __restrict__ p1,
    const float* __restrict__ p2, const float* __restrict__ p3,
    const float* __restrict__ p4, float* __restrict__ out)
{
    __shared__ float s_lx[CROP], s_ly[CROP];
    __shared__ int   s_x0[CROP], s_x1[CROP];   // float4 offsets within a row
    __shared__ int   s_r0[CROP], s_r1[CROP];   // float4 offsets of rows
    __shared__ int   s_vx[CROP], s_vy[CROP];
    __shared__ int   s_xlist[CROP + 3], s_xinv[CROP];
    __shared__ int   s_nx, s_ninv;

    int tid  = threadIdx.x;
    int b    = blockIdx.x >> 1;
    int half = blockIdx.x & 1;
    float4 box = g_boxes[b];
    int lev = g_level[b];

    const float* feat;
    int S;
    switch (lev) {
        case 0:  feat = p0; S = 256; break;
        case 1:  feat = p1; S = 128; break;
        case 2:  feat = p2; S = 64;  break;
        case 3:  feat = p3; S = 32;  break;
        default: feat = p4; S = 16;  break;
    }
    float hf = (float)(S - 1);

    if (tid < 2 * CROP) {
        int i = tid;
        bool isy = i >= CROP;
        int k = isy ? i - CROP : i;
        float a1 = isy ? box.y : box.x;
        float a2 = isy ? box.w : box.z;
        // reference normalizes then rescales by the same (S-1) factor
        float n1 = a1 / hf, n2 = a2 / hf;
        float t = (float)k / 13.0f;
        float s = (n1 + (n2 - n1) * t) * hf;
        int valid = (s >= 0.0f && s <= hf) ? 1 : 0;
        float f0 = floorf(s);
        float l = s - f0;
        int i0 = (int)fminf(fmaxf(f0, 0.0f), hf);
        int i1 = (int)fminf(fmaxf(f0 + 1.0f, 0.0f), hf);
        if (isy) {
            s_ly[k] = l; s_vy[k] = valid;
            s_r0[k] = i0 * S * (CH / 4);
            s_r1[k] = i1 * S * (CH / 4);
        } else {
            s_lx[k] = l; s_vx[k] = valid;
            s_x0[k] = i0 * (CH / 4);
            s_x1[k] = i1 * (CH / 4);
        }
    }
    __syncthreads();
    if (tid == 0) {
        int n = 0, m = 0;
#pragma unroll
        for (int i = 0; i < CROP; i++) {
            if (s_vx[i]) s_xlist[n++] = i;
            else         s_xinv[m++]  = i;
        }
        s_nx = n; s_ninv = m;
        if (n > 0) {                      // pad to multiple of 4
            int last = s_xlist[n - 1];
            while (n & 3) s_xlist[n++] = last;
        }
    }
    __syncthreads();

    int cg = tid & 63;           // channel group (float4)
    int rg = tid >> 6;           // row group (0..1)
    const float4* fp = (const float4*)feat;
    const float4 zero4 = make_float4(0.f, 0.f, 0.f, 0.f);
    int nv = s_nx, ni = s_ninv;
    int nvp = (nv + 3) & ~3;
    int ybase = half * 7;        // rows [ybase, ybase+7)

    for (int yi = ybase + rg; yi < ybase + 7; yi += 2) {
        float4* orow = (float4*)(out + (((size_t)b * CROP + yi) * CROP) * CH) + cg;

        if (!s_vy[yi]) {
#pragma unroll
            for (int xi = 0; xi < CROP; xi++)
                __stcs(orow + (size_t)xi * 64, zero4);
            continue;
        }

        // zero-fill invalid columns (no loads)
        for (int k = 0; k < ni; k++)
            __stcs(orow + (size_t)s_xinv[k] * 64, zero4);

        int r0 = s_r0[yi] + cg;
        int r1 = s_r1[yi] + cg;
        float ly = s_ly[yi];

        for (int j = 0; j < nvp; j += 4) {
            int   xq[4];
            int   q0[4], q1[4];
            float lx[4];
#pragma unroll
            for (int q = 0; q < 4; q++) {
                xq[q] = s_xlist[j + q];
                q0[q] = s_x0[xq[q]];
                q1[q] = s_x1[xq[q]];
                lx[q] = s_lx[xq[q]];
            }
            float4 F00[4], F01[4], F10[4], F11[4];
#pragma unroll
            for (int q = 0; q < 4; q++) {
                F00[q] = __ldg(fp + r0 + q0[q]);
                F01[q] = __ldg(fp + r0 + q1[q]);
                F10[q] = __ldg(fp + r1 + q0[q]);
                F11[q] = __ldg(fp + r1 + q1[q]);
            }
#pragma unroll
            for (int q = 0; q < 4; q++) {
                float4 v;
                float t, bo;
                t = F00[q].x + (F01[q].x - F00[q].x) * lx[q];
                bo = F10[q].x + (F11[q].x - F10[q].x) * lx[q];
                v.x = t + (bo - t) * ly;
                t = F00[q].y + (F01[q].y - F00[q].y) * lx[q];
                bo = F10[q].y + (F11[q].y - F10[q].y) * lx[q];
                v.y = t + (bo - t) * ly;
                t = F00[q].z + (F01[q].z - F00[q].z) * lx[q];
                bo = F10[q].z + (F11[q].z - F10[q].z) * lx[q];
                v.z = t + (bo - t) * ly;
                t = F00[q].w + (F01[q].w - F00[q].w) * lx[q];
                bo = F10[q].w + (F11[q].w - F10[q].w) * lx[q];
                v.w = t + (bo - t) * ly;
                __stcs(orow + (size_t)xq[q] * 64, v);
            }
        }
    }
}

// ---------------------------------------------------------------------------
extern "C" void kernel_launch(void* const* d_in, const int* in_sizes, int n_in,
                              void* d_out, int out_size) {
    const float* det = (const float*)d_in[0];
    const float* p0  = (const float*)d_in[1];
    const float* p1  = (const float*)d_in[2];
    const float* p2  = (const float*)d_in[3];
    const float* p3  = (const float*)d_in[4];
    const float* p4  = (const float*)d_in[5];
    float* out = (float*)d_out;

    k_scores<<<(NDET * 32 + 255) / 256, 256>>>(det);
    dim3 rgrid(NDET / RPB, NDET / JCH);   // 625 x 2
    k_rank<<<rgrid, 512>>>();
    k_scatter<<<(NDET + 255) / 256, 256>>>();
    k_level_sort<<<1, 1024>>>(det);
    k_main<<<TOPK * 2, 128>>>(p0, p1, p2, p3, p4, out);
}

// round 15
// speedup vs baseline: 1.0892x; 1.0726x over previous
#include <cuda_runtime.h>
#include <float.h>

#define NDET      5000
#define TOPK      1000
#define NCLS      80
#define DETSTRIDE 84
#define CH        256
#define CROP      14

// Scratch (no allocations allowed in kernel_launch)
__device__ float g_scores[NDET];
__device__ int   g_sel[TOPK];            // rank -> original detection row
__device__ float4 g_boxes[TOPK];         // boxes after stable level sort
__device__ int    g_level[TOPK];

// ---------------------------------------------------------------------------
// K1: per-row max over 80 class scores. Warp per row, coalesced reads.
// ---------------------------------------------------------------------------
__global__ void __launch_bounds__(256) k_scores(const float* __restrict__ det) {
    int warp = (blockIdx.x * blockDim.x + threadIdx.x) >> 5;
    int lane = threadIdx.x & 31;
    if (warp >= NDET) return;
    const float* p = det + (size_t)warp * DETSTRIDE + 4;
    float m = -FLT_MAX;
    for (int i = lane; i < NCLS; i += 32) m = fmaxf(m, p[i]);
#pragma unroll
    for (int off = 16; off > 0; off >>= 1)
        m = fmaxf(m, __shfl_xor_sync(0xffffffffu, m, off));
    if (lane == 0) g_scores[warp] = m;
}

// ---------------------------------------------------------------------------
// K2: exact jax.lax.top_k via rank counting. 8 rows per block (5000/8 = 625
// blocks, exact), scores staged in shared once; 512 threads split compares.
// ---------------------------------------------------------------------------
#define RPB 8
__global__ void __launch_bounds__(512) k_rank() {
    __shared__ float s[NDET];
    __shared__ int blockcnt[RPB];
    int tid = threadIdx.x;
    for (int j = tid; j < NDET; j += 512) s[j] = g_scores[j];
    if (tid < RPB) blockcnt[tid] = 0;
    __syncthreads();

    int base = blockIdx.x * RPB;
    float sr[RPB];
#pragma unroll
    for (int k = 0; k < RPB; k++) sr[k] = s[base + k];

    int cnt[RPB];
#pragma unroll
    for (int k = 0; k < RPB; k++) cnt[k] = 0;

    for (int j = tid; j < NDET; j += 512) {
        float sj = s[j];
#pragma unroll
        for (int k = 0; k < RPB; k++)
            cnt[k] += (sj > sr[k] || (sj == sr[k] && j < base + k)) ? 1 : 0;
    }
#pragma unroll
    for (int k = 0; k < RPB; k++) {
#pragma unroll
        for (int off = 16; off > 0; off >>= 1)
            cnt[k] += __shfl_down_sync(0xffffffffu, cnt[k], off);
    }
    if ((tid & 31) == 0) {
#pragma unroll
        for (int k = 0; k < RPB; k++) atomicAdd(&blockcnt[k], cnt[k]);
    }
    __syncthreads();
    if (tid < RPB) {
        int rank = blockcnt[tid];
        if (rank < TOPK) g_sel[rank] = base + tid;
    }
}

// ---------------------------------------------------------------------------
// K3: fused level computation + stable counting sort by level (single block).
// ---------------------------------------------------------------------------
__global__ void __launch_bounds__(1024) k_level_sort(const float* __restrict__ det) {
    int r = threadIdx.x;
    float x1 = 0, y1 = 0, x2 = 0, y2 = 0;
    int lev = 0;
    unsigned long long onehot = 0ULL;
    if (r < TOPK) {
        const float* p = det + (size_t)g_sel[r] * DETSTRIDE;
        x1 = p[0]; y1 = p[1]; x2 = p[2]; y2 = p[3];
        float size = sqrtf((x2 - x1) * (y2 - y1));
        float lv = floorf(1.0f + log2f(size / 224.0f + 1e-7f));
        lv = fminf(fmaxf(lv, 0.0f), 4.0f);
        lev = (int)lv;
        onehot = 1ULL << (10 * lev);
    }
    unsigned long long v = onehot;
    int lane = r & 31;
#pragma unroll
    for (int off = 1; off < 32; off <<= 1) {
        unsigned long long n = __shfl_up_sync(0xffffffffu, v, off);
        if (lane >= off) v += n;
    }
    __shared__ unsigned long long warpsum[32];
    int wid = r >> 5;
    if (lane == 31) warpsum[wid] = v;
    __syncthreads();
    if (r < 32) {
        unsigned long long w = warpsum[r];
#pragma unroll
        for (int off = 1; off < 32; off <<= 1) {
            unsigned long long n = __shfl_up_sync(0xffffffffu, w, off);
            if (r >= off) w += n;
        }
        warpsum[r] = w;
    }
    __syncthreads();
    unsigned long long incl = v + (wid > 0 ? warpsum[wid - 1] : 0ULL);
    unsigned long long total = warpsum[31];
    unsigned long long excl = incl - onehot;
    if (r < TOPK) {
        int before = 0;
#pragma unroll
        for (int l = 0; l < 4; l++)
            if (l < lev) before += (int)((total >> (10 * l)) & 1023ULL);
        int pos = before + (int)((excl >> (10 * lev)) & 1023ULL);
        g_boxes[pos] = make_float4(x1, y1, x2, y2);
        g_level[pos] = lev;
    }
}

// ---------------------------------------------------------------------------
// K4: crop_and_resize. 128-thread block = (box, y-half), fixed grid 2000.
// Valid x-columns compacted + padded to multiple of 6; hot loop does
// 6 points/iter = 24 independent LDG.128 per thread.
// launch_bounds(128,4): allow natural regs (<=128), 4 blocks/SM,
// in-flight = 16 warps x 24 = 384 loads.
// ---------------------------------------------------------------------------
#define UW 6
__global__ void __launch_bounds__(128, 4) k_main(
    const float* __restrict__ p0, const float* __restrict__ p1,
    const float* __restrict__ p2, const float* __restrict__ p3,
    const float* __restrict__ p4, float* __restrict__ out)
{
    __shared__ float s_lx[CROP], s_ly[CROP];
    __shared__ int   s_x0[CROP], s_x1[CROP];   // float4 offsets within a row
    __shared__ int   s_r0[CROP], s_r1[CROP];   // float4 offsets of rows
    __shared__ int   s_vx[CROP], s_vy[CROP];
    __shared__ int   s_xlist[CROP + UW - 1], s_xinv[CROP];
    __shared__ int   s_nx, s_ninv;

    int tid  = threadIdx.x;
    int b    = blockIdx.x >> 1;
    int half = blockIdx.x & 1;
    float4 box = g_boxes[b];
    int lev = g_level[b];

    const float* feat;
    int S;
    switch (lev) {
        case 0:  feat = p0; S = 256; break;
        case 1:  feat = p1; S = 128; break;
        case 2:  feat = p2; S = 64;  break;
        case 3:  feat = p3; S = 32;  break;
        default: feat = p4; S = 16;  break;
    }
    float hf = (float)(S - 1);

    if (tid < 2 * CROP) {
        int i = tid;
        bool isy = i >= CROP;
        int k = isy ? i - CROP : i;
        float a1 = isy ? box.y : box.x;
        float a2 = isy ? box.w : box.z;
        // reference normalizes then rescales by the same (S-1) factor
        float n1 = a1 / hf, n2 = a2 / hf;
        float t = (float)k / 13.0f;
        float s = (n1 + (n2 - n1) * t) * hf;
        int valid = (s >= 0.0f && s <= hf) ? 1 : 0;
        float f0 = floorf(s);
        float l = s - f0;
        int i0 = (int)fminf(fmaxf(f0, 0.0f), hf);
        int i1 = (int)fminf(fmaxf(f0 + 1.0f, 0.0f), hf);
        if (isy) {
            s_ly[k] = l; s_vy[k] = valid;
            s_r0[k] = i0 * S * (CH / 4);
            s_r1[k] = i1 * S * (CH / 4);
        } else {
            s_lx[k] = l; s_vx[k] = valid;
            s_x0[k] = i0 * (CH / 4);
            s_x1[k] = i1 * (CH / 4);
        }
    }
    __syncthreads();
    if (tid == 0) {
        int n = 0, m = 0;
#pragma unroll
        for (int i = 0; i < CROP; i++) {
            if (s_vx[i]) s_xlist[n++] = i;
            else         s_xinv[m++]  = i;
        }
        s_nx = n; s_ninv = m;
        if (n > 0) {                      // pad to multiple of UW
            int last = s_xlist[n - 1];
            while (n % UW) s_xlist[n++] = last;
        }
    }
    __syncthreads();

    int cg = tid & 63;           // channel group (float4)
    int rg = tid >> 6;           // row group (0..1)
    const float4* fp = (const float4*)feat;
    const float4 zero4 = make_float4(0.f, 0.f, 0.f, 0.f);
    int nv = s_nx, ni = s_ninv;
    int nvp = ((nv + UW - 1) / UW) * UW;
    int ybase = half * 7;        // rows [ybase, ybase+7)

    for (int yi = ybase + rg; yi < ybase + 7; yi += 2) {
        float4* orow = (float4*)(out + (((size_t)b * CROP + yi) * CROP) * CH) + cg;

        if (!s_vy[yi]) {
#pragma unroll
            for (int xi = 0; xi < CROP; xi++)
                __stcs(orow + (size_t)xi * 64, zero4);
            continue;
        }

        // zero-fill invalid columns (no loads)
        for (int k = 0; k < ni; k++)
            __stcs(orow + (size_t)s_xinv[k] * 64, zero4);

        int r0 = s_r0[yi] + cg;
        int r1 = s_r1[yi] + cg;
        float ly = s_ly[yi];

        for (int j = 0; j < nvp; j += UW) {
            int   xq[UW];
            int   q0[UW], q1[UW];
            float lx[UW];
#pragma unroll
            for (int q = 0; q < UW; q++) {
                xq[q] = s_xlist[j + q];
                q0[q] = s_x0[xq[q]];
                q1[q] = s_x1[xq[q]];
                lx[q] = s_lx[xq[q]];
            }
            float4 F00[UW], F01[UW], F10[UW], F11[UW];
#pragma unroll
            for (int q = 0; q < UW; q++) {
                F00[q] = __ldg(fp + r0 + q0[q]);
                F01[q] = __ldg(fp + r0 + q1[q]);
                F10[q] = __ldg(fp + r1 + q0[q]);
                F11[q] = __ldg(fp + r1 + q1[q]);
            }
#pragma unroll
            for (int q = 0; q < UW; q++) {
                float4 v;
                float t, bo;
                t = F00[q].x + (F01[q].x - F00[q].x) * lx[q];
                bo = F10[q].x + (F11[q].x - F10[q].x) * lx[q];
                v.x = t + (bo - t) * ly;
                t = F00[q].y + (F01[q].y - F00[q].y) * lx[q];
                bo = F10[q].y + (F11[q].y - F10[q].y) * lx[q];
                v.y = t + (bo - t) * ly;
                t = F00[q].z + (F01[q].z - F00[q].z) * lx[q];
                bo = F10[q].z + (F11[q].z - F10[q].z) * lx[q];
                v.z = t + (bo - t) * ly;
                t = F00[q].w + (F01[q].w - F00[q].w) * lx[q];
                bo = F10[q].w + (F11[q].w - F10[q].w) * lx[q];
                v.w = t + (bo - t) * ly;
                __stcs(orow + (size_t)xq[q] * 64, v);
            }
        }
    }
}

// ---------------------------------------------------------------------------
extern "C" void kernel_launch(void* const* d_in, const int* in_sizes, int n_in,
                              void* d_out, int out_size) {
    const float* det = (const float*)d_in[0];
    const float* p0  = (const float*)d_in[1];
    const float* p1  = (const float*)d_in[2];
    const float* p2  = (const float*)d_in[3];
    const float* p3  = (const float*)d_in[4];
    const float* p4  = (const float*)d_in[5];
    float* out = (float*)d_out;

    k_scores<<<(NDET * 32 + 255) / 256, 256>>>(det);
    k_rank<<<NDET / RPB, 512>>>();
    k_level_sort<<<1, 1024>>>(det);
    k_main<<<TOPK * 2, 128>>>(p0, p1, p2, p3, p4, out);
}

// round 16
// speedup vs baseline: 1.0898x; 1.0005x over previous
#include <cuda_runtime.h>
#include <float.h>

#define NDET      5000
#define TOPK      1000
#define NCLS      80
#define DETSTRIDE 84
#define CH        256
#define CROP      14

// Scratch (no allocations allowed in kernel_launch)
__device__ float g_scores[NDET];
__device__ int   g_sel[TOPK];            // rank -> original detection row
__device__ float4 g_boxes[TOPK];         // boxes after stable level sort
__device__ int    g_level[TOPK];

// ---------------------------------------------------------------------------
// K1: per-row max over 80 class scores. Warp per row, coalesced reads.
// ---------------------------------------------------------------------------
__global__ void __launch_bounds__(256) k_scores(const float* __restrict__ det) {
    int warp = (blockIdx.x * blockDim.x + threadIdx.x) >> 5;
    int lane = threadIdx.x & 31;
    if (warp >= NDET) return;
    const float* p = det + (size_t)warp * DETSTRIDE + 4;
    float m = -FLT_MAX;
    for (int i = lane; i < NCLS; i += 32) m = fmaxf(m, p[i]);
#pragma unroll
    for (int off = 16; off > 0; off >>= 1)
        m = fmaxf(m, __shfl_xor_sync(0xffffffffu, m, off));
    if (lane == 0) g_scores[warp] = m;
}

// ---------------------------------------------------------------------------
// K2: exact jax.lax.top_k via rank counting. 8 rows per block (5000/8 = 625
// blocks, exact). No smem staging: g_scores (20KB) is L2-resident and
// broadcast to all blocks; 1024 threads -> 5 j-iterations each.
// rank(r) = #{j : s_j > s_r} + #{j < r : s_j == s_r}
// ---------------------------------------------------------------------------
#define RPB 8
__global__ void __launch_bounds__(1024) k_rank() {
    __shared__ int blockcnt[RPB];
    int tid = threadIdx.x;
    int base = blockIdx.x * RPB;
    if (tid < RPB) blockcnt[tid] = 0;

    float sr[RPB];
#pragma unroll
    for (int k = 0; k < RPB; k++) sr[k] = __ldg(&g_scores[base + k]);

    int cnt[RPB];
#pragma unroll
    for (int k = 0; k < RPB; k++) cnt[k] = 0;

    __syncthreads();
#pragma unroll
    for (int it = 0; it < (NDET + 1023) / 1024; it++) {
        int j = it * 1024 + tid;
        if (j < NDET) {
            float sj = __ldg(&g_scores[j]);
#pragma unroll
            for (int k = 0; k < RPB; k++)
                cnt[k] += (sj > sr[k] || (sj == sr[k] && j < base + k)) ? 1 : 0;
        }
    }
#pragma unroll
    for (int k = 0; k < RPB; k++) {
#pragma unroll
        for (int off = 16; off > 0; off >>= 1)
            cnt[k] += __shfl_down_sync(0xffffffffu, cnt[k], off);
    }
    if ((tid & 31) == 0) {
#pragma unroll
        for (int k = 0; k < RPB; k++)
            if (cnt[k] > 0) atomicAdd(&blockcnt[k], cnt[k]);
    }
    __syncthreads();
    if (tid < RPB) {
        int rank = blockcnt[tid];
        if (rank < TOPK) g_sel[rank] = base + tid;
    }
}

// ---------------------------------------------------------------------------
// K3: fused level computation + stable counting sort by level (single block).
// ---------------------------------------------------------------------------
__global__ void __launch_bounds__(1024) k_level_sort(const float* __restrict__ det) {
    int r = threadIdx.x;
    float x1 = 0, y1 = 0, x2 = 0, y2 = 0;
    int lev = 0;
    unsigned long long onehot = 0ULL;
    if (r < TOPK) {
        const float* p = det + (size_t)g_sel[r] * DETSTRIDE;
        x1 = p[0]; y1 = p[1]; x2 = p[2]; y2 = p[3];
        float size = sqrtf((x2 - x1) * (y2 - y1));
        float lv = floorf(1.0f + log2f(size / 224.0f + 1e-7f));
        lv = fminf(fmaxf(lv, 0.0f), 4.0f);
        lev = (int)lv;
        onehot = 1ULL << (10 * lev);
    }
    unsigned long long v = onehot;
    int lane = r & 31;
#pragma unroll
    for (int off = 1; off < 32; off <<= 1) {
        unsigned long long n = __shfl_up_sync(0xffffffffu, v, off);
        if (lane >= off) v += n;
    }
    __shared__ unsigned long long warpsum[32];
    int wid = r >> 5;
    if (lane == 31) warpsum[wid] = v;
    __syncthreads();
    if (r < 32) {
        unsigned long long w = warpsum[r];
#pragma unroll
        for (int off = 1; off < 32; off <<= 1) {
            unsigned long long n = __shfl_up_sync(0xffffffffu, w, off);
            if (r >= off) w += n;
        }
        warpsum[r] = w;
    }
    __syncthreads();
    unsigned long long incl = v + (wid > 0 ? warpsum[wid - 1] : 0ULL);
    unsigned long long total = warpsum[31];
    unsigned long long excl = incl - onehot;
    if (r < TOPK) {
        int before = 0;
#pragma unroll
        for (int l = 0; l < 4; l++)
            if (l < lev) before += (int)((total >> (10 * l)) & 1023ULL);
        int pos = before + (int)((excl >> (10 * lev)) & 1023ULL);
        g_boxes[pos] = make_float4(x1, y1, x2, y2);
        g_level[pos] = lev;
    }
}

// ---------------------------------------------------------------------------
// K4: crop_and_resize. EXACT R15 config (best measured: 43.1us).
// 128-thread block = (box, y-half), grid 2000, launch_bounds(128,4).
// Valid x-columns compacted + padded to multiple of 6; 6 points/iter =
// 24 independent LDG.128 per thread (natural regs, no squeeze).
// ---------------------------------------------------------------------------
#define UW 6
__global__ void __launch_bounds__(128, 4) k_main(
    const float* __restrict__ p0, const float* __restrict__ p1,
    const float* __restrict__ p2, const float* __restrict__ p3,
    const float* __restrict__ p4, float* __restrict__ out)
{
    __shared__ float s_lx[CROP], s_ly[CROP];
    __shared__ int   s_x0[CROP], s_x1[CROP];   // float4 offsets within a row
    __shared__ int   s_r0[CROP], s_r1[CROP];   // float4 offsets of rows
    __shared__ int   s_vx[CROP], s_vy[CROP];
    __shared__ int   s_xlist[CROP + UW - 1], s_xinv[CROP];
    __shared__ int   s_nx, s_ninv;

    int tid  = threadIdx.x;
    int b    = blockIdx.x >> 1;
    int half = blockIdx.x & 1;
    float4 box = g_boxes[b];
    int lev = g_level[b];

    const float* feat;
    int S;
    switch (lev) {
        case 0:  feat = p0; S = 256; break;
        case 1:  feat = p1; S = 128; break;
        case 2:  feat = p2; S = 64;  break;
        case 3:  feat = p3; S = 32;  break;
        default: feat = p4; S = 16;  break;
    }
    float hf = (float)(S - 1);

    if (tid < 2 * CROP) {
        int i = tid;
        bool isy = i >= CROP;
        int k = isy ? i - CROP : i;
        float a1 = isy ? box.y : box.x;
        float a2 = isy ? box.w : box.z;
        // reference normalizes then rescales by the same (S-1) factor
        float n1 = a1 / hf, n2 = a2 / hf;
        float t = (float)k / 13.0f;
        float s = (n1 + (n2 - n1) * t) * hf;
        int valid = (s >= 0.0f && s <= hf) ? 1 : 0;
        float f0 = floorf(s);
        float l = s - f0;
        int i0 = (int)fminf(fmaxf(f0, 0.0f), hf);
        int i1 = (int)fminf(fmaxf(f0 + 1.0f, 0.0f), hf);
        if (isy) {
            s_ly[k] = l; s_vy[k] = valid;
            s_r0[k] = i0 * S * (CH / 4);
            s_r1[k] = i1 * S * (CH / 4);
        } else {
            s_lx[k] = l; s_vx[k] = valid;
            s_x0[k] = i0 * (CH / 4);
            s_x1[k] = i1 * (CH / 4);
        }
    }
    __syncthreads();
    if (tid == 0) {
        int n = 0, m = 0;
#pragma unroll
        for (int i = 0; i < CROP; i++) {
            if (s_vx[i]) s_xlist[n++] = i;
            else         s_xinv[m++]  = i;
        }
        s_nx = n; s_ninv = m;
        if (n > 0) {                      // pad to multiple of UW
            int last = s_xlist[n - 1];
            while (n % UW) s_xlist[n++] = last;
        }
    }
    __syncthreads();

    int cg = tid & 63;           // channel group (float4)
    int rg = tid >> 6;           // row group (0..1)
    const float4* fp = (const float4*)feat;
    const float4 zero4 = make_float4(0.f, 0.f, 0.f, 0.f);
    int nv = s_nx, ni = s_ninv;
    int nvp = ((nv + UW - 1) / UW) * UW;
    int ybase = half * 7;        // rows [ybase, ybase+7)

    for (int yi = ybase + rg; yi < ybase + 7; yi += 2) {
        float4* orow = (float4*)(out + (((size_t)b * CROP + yi) * CROP) * CH) + cg;

        if (!s_vy[yi]) {
#pragma unroll
            for (int xi = 0; xi < CROP; xi++)
                __stcs(orow + (size_t)xi * 64, zero4);
            continue;
        }

        // zero-fill invalid columns (no loads)
        for (int k = 0; k < ni; k++)
            __stcs(orow + (size_t)s_xinv[k] * 64, zero4);

        int r0 = s_r0[yi] + cg;
        int r1 = s_r1[yi] + cg;
        float ly = s_ly[yi];

        for (int j = 0; j < nvp; j += UW) {
            int   xq[UW];
            int   q0[UW], q1[UW];
            float lx[UW];
#pragma unroll
            for (int q = 0; q < UW; q++) {
                xq[q] = s_xlist[j + q];
                q0[q] = s_x0[xq[q]];
                q1[q] = s_x1[xq[q]];
                lx[q] = s_lx[xq[q]];
            }
            float4 F00[UW], F01[UW], F10[UW], F11[UW];
#pragma unroll
            for (int q = 0; q < UW; q++) {
                F00[q] = __ldg(fp + r0 + q0[q]);
                F01[q] = __ldg(fp + r0 + q1[q]);
                F10[q] = __ldg(fp + r1 + q0[q]);
                F11[q] = __ldg(fp + r1 + q1[q]);
            }
#pragma unroll
            for (int q = 0; q < UW; q++) {
                float4 v;
                float t, bo;
                t = F00[q].x + (F01[q].x - F00[q].x) * lx[q];
                bo = F10[q].x + (F11[q].x - F10[q].x) * lx[q];
                v.x = t + (bo - t) * ly;
                t = F00[q].y + (F01[q].y - F00[q].y) * lx[q];
                bo = F10[q].y + (F11[q].y - F10[q].y) * lx[q];
                v.y = t + (bo - t) * ly;
                t = F00[q].z + (F01[q].z - F00[q].z) * lx[q];
                bo = F10[q].z + (F11[q].z - F10[q].z) * lx[q];
                v.z = t + (bo - t) * ly;
                t = F00[q].w + (F01[q].w - F00[q].w) * lx[q];
                bo = F10[q].w + (F11[q].w - F10[q].w) * lx[q];
                v.w = t + (bo - t) * ly;
                __stcs(orow + (size_t)xq[q] * 64, v);
            }
        }
    }
}

// ---------------------------------------------------------------------------
extern "C" void kernel_launch(void* const* d_in, const int* in_sizes, int n_in,
                              void* d_out, int out_size) {
    const float* det = (const float*)d_in[0];
    const float* p0  = (const float*)d_in[1];
    const float* p1  = (const float*)d_in[2];
    const float* p2  = (const float*)d_in[3];
    const float* p3  = (const float*)d_in[4];
    const float* p4  = (const float*)d_in[5];
    float* out = (float*)d_out;

    k_scores<<<(NDET * 32 + 255) / 256, 256>>>(det);
    k_rank<<<NDET / RPB, 1024>>>();
    k_level_sort<<<1, 1024>>>(det);
    k_main<<<TOPK * 2, 128>>>(p0, p1, p2, p3, p4, out);
}